// round 6
// baseline (speedup 1.0000x reference)
#include <cuda_runtime.h>
#include <cuda_fp16.h>
#include <math.h>
#include <stdint.h>

#define NB 16
#define NC 256
#define NH 64
#define NW 64
#define NTAP 9
#define SEXP (NC*NC*NTAP)
#define QP 66
#define QN (QP*QP)                /* 4356 padded pixels */
#define TILE_M 128
#define TILE_N 256
#define KC 32
#define NSTEPS (NTAP*(NC/KC))     /* 72 */
#define A_BYTES (TILE_M*KC*2)     /* 8192, fragment-major contiguous */
#define B_PITCH 80                /* 64B data + 16B pad per pixel row */
#define B_BYTES (TILE_N*B_PITCH)  /* 20480 */
#define STAGE_BYTES (A_BYTES + B_BYTES)   /* 28672 */
#define STAGES 3
#define SMEM_TOTAL (STAGES * STAGE_BYTES) /* 86016 */
#define QTILES ((QN + TILE_N - 1) / TILE_N)  /* 18 */

__device__ float g_pooled[NB*NC];
__device__ float g_routing[NB*4];
// A, fragment-major fp16: [b][t][otile(2)][chunk(8)][kk(2)][mblk(8)][lane(32)][reg(4)][e(2)]
__device__ __align__(1024) __half g_weff[(size_t)NB*NTAP*NC*NC];
// B fp16: [b][q][c_perm], perm within each 16-group: pos = 4*tig + 2*khi + e
__device__ __align__(1024) __half g_xpad[(size_t)NB*QN*NC];

// ------------------------------------------------------------------ helpers
__device__ __forceinline__ uint32_t s2u(const void* p){
    uint32_t a;
    asm("{ .reg .u64 t; cvta.to.shared.u64 t, %1; cvt.u32.u64 %0, t; }" : "=r"(a) : "l"(p));
    return a;
}
__device__ __forceinline__ void cp16(uint32_t dst, const void* src, int szbytes){
    asm volatile("cp.async.cg.shared.global [%0], [%1], 16, %2;"
                 :: "r"(dst), "l"(src), "r"(szbytes) : "memory");
}
__device__ __forceinline__ void cp_commit(){
    asm volatile("cp.async.commit_group;" ::: "memory");
}
template<int N> __device__ __forceinline__ void cp_wait(){
    asm volatile("cp.async.wait_group %0;" :: "n"(N) : "memory");
}
__device__ __forceinline__ void mma16(float* d, const uint4 a, const uint2 b){
    asm volatile("mma.sync.aligned.m16n8k16.row.col.f32.f16.f16.f32 "
        "{%0,%1,%2,%3}, {%4,%5,%6,%7}, {%8,%9}, {%0,%1,%2,%3};"
        : "+f"(d[0]), "+f"(d[1]), "+f"(d[2]), "+f"(d[3])
        : "r"(a.x), "r"(a.y), "r"(a.z), "r"(a.w), "r"(b.x), "r"(b.y));
}

// ------------------------------------------------------------------ prep
__global__ void pool_kernel(const float* __restrict__ x) {
    int bc = blockIdx.x;
    const float4* p = (const float4*)(x + (size_t)bc * NH * NW);
    float s = 0.f;
    for (int i = threadIdx.x; i < NH*NW/4; i += blockDim.x) {
        float4 v = p[i];
        s += v.x + v.y + v.z + v.w;
    }
    #pragma unroll
    for (int o = 16; o; o >>= 1) s += __shfl_xor_sync(0xffffffffu, s, o);
    __shared__ float red[4];
    if ((threadIdx.x & 31) == 0) red[threadIdx.x >> 5] = s;
    __syncthreads();
    if (threadIdx.x == 0)
        g_pooled[bc] = (red[0]+red[1]+red[2]+red[3]) * (1.0f/(NH*NW));
}

__global__ void route_kernel(const float* __restrict__ wr, const float* __restrict__ br) {
    int t = threadIdx.x;
    if (t >= NB*4) return;
    int b = t >> 2, e = t & 3;
    float acc = br[e];
    const float* pw = wr + e*NC;
    const float* pp = g_pooled + b*NC;
    #pragma unroll 8
    for (int c = 0; c < NC; ++c) acc = fmaf(pp[c], pw[c], acc);
    g_routing[t] = 1.f/(1.f + expf(-acc));
}

// weff fragment-major fp16 per m16n8k16 A-fragment mapping
__global__ void fold_kernel(const float* __restrict__ we) {
    int lin = blockIdx.x * blockDim.x + threadIdx.x;
    if (lin >= NTAP*NC*NC) return;
    int c = lin & 255, o = (lin >> 8) & 255, t = lin >> 16;
    size_t wi = ((size_t)o*NC + c)*NTAP + t;
    float w0 = we[wi], w1 = we[wi + (size_t)SEXP];
    float w2 = we[wi + 2*(size_t)SEXP], w3 = we[wi + 3*(size_t)SEXP];

    int chunk = c >> 5, cc = c & 31;
    int kk = cc >> 4, kc = cc & 15;
    int tig = (kc >> 1) & 3, e = kc & 1, khi = kc >> 3;
    int otile = o >> 7, mblk = (o >> 4) & 7, g8 = o & 7, ohi = (o >> 3) & 1;
    int reg  = khi*2 + ohi;
    int lane = g8*4 + tig;
    size_t inner = (size_t)((kk*8 + mblk)*32 + lane)*8 + reg*2 + e;
    size_t base  = ((((size_t)t*2 + otile)*8 + chunk)*4096) + inner;
    #pragma unroll
    for (int b = 0; b < NB; ++b) {
        const float* r = g_routing + b*4;
        g_weff[(size_t)b*(NTAP*NC*NC) + base] =
            __float2half_rn(w0*r[0] + w1*r[1] + w2*r[2] + w3*r[3]);
    }
}

// x_pad[b][q][c_perm] fp16, q over 66x66 grid, zero ring.
// perm within each 16-group: pos = 4*((k&7)>>1) + 2*((k>>3)&1) + (k&1)
__global__ void xpad_kernel(const float* __restrict__ x) {
    __shared__ float s[64*65];
    int c0 = blockIdx.x * 64, hp = blockIdx.y, b = blockIdx.z;
    int h = hp - 1;
    bool hv = (h >= 0 && h < NH);
    if (hv) {
        const float* xp = x + ((size_t)(b*NC + c0))*(NH*NW) + (size_t)h*NW;
        for (int j = 0; j < 16; ++j) {
            int idx = j*256 + threadIdx.x;
            int i = idx >> 6, w = idx & 63;
            s[w*65 + i] = xp[(size_t)i*(NH*NW) + w];
        }
    }
    __syncthreads();
    __half* op = g_xpad + ((size_t)b*QN + (size_t)hp*QP)*NC + c0;
    for (int j = 0; j < 17; ++j) {
        int idx = j*256 + threadIdx.x;
        if (idx >= QP*64) break;
        int i = idx & 63, wp = idx >> 6;
        float v = 0.f;
        if (hv && wp >= 1 && wp <= 64) v = s[(wp-1)*65 + i];
        int kc = i & 15;
        int ipos = (i & ~15) | (4*((kc & 7) >> 1) + 2*(kc >> 3) + (kc & 1));
        op[(size_t)wp*NC + ipos] = __float2half_rn(v);
    }
}

// ------------------------------------------------------------------ conv GEMM
__device__ __forceinline__ void load_stage(uint32_t stBase, int step, int b,
                                           int otile, int q0, int tid)
{
    int t = step >> 3;
    int chunk = step & 7;
    int dh = t / 3, dw = t - dh*3;
    int qb = q0 + (dh-1)*QP + (dw-1);
    const __half* aG = g_weff + (size_t)b*(NTAP*NC*NC)
                     + ((((size_t)t*2 + otile)*8 + chunk)*4096);
    const __half* bG = g_xpad + (size_t)b*QN*NC + chunk*KC;
    // A: 512 linear 16B segs (8 KB). B: 256 rows x 4 segs.
    #pragma unroll
    for (int jj = 0; jj < 6; ++jj) {
        int seg = tid + jj*256;
        if (seg < 512) {
            cp16(stBase + seg*16, aG + seg*8, 16);
        } else {
            int k = seg - 512;
            int row = k >> 2, j = k & 3;
            int q = qb + row;
            bool v = ((unsigned)q < (unsigned)QN);
            const __half* src = bG + (size_t)(v ? q : 0)*NC + j*8;
            cp16(stBase + A_BYTES + row*B_PITCH + j*16, src, v ? 16 : 0);
        }
    }
}

__global__ void __launch_bounds__(256, 2)
conv_mma_kernel(const float* __restrict__ gamma, const float* __restrict__ beta,
                const float* __restrict__ mean,  const float* __restrict__ var,
                float* __restrict__ out)
{
    extern __shared__ __align__(128) char smem[];
    const uint32_t sb = s2u(smem);
    const int tid = threadIdx.x, wid = tid >> 5, lid = tid & 31;
    const int wm = wid >> 2, wn = wid & 3;        // warp grid 2 x 4
    const int g = lid >> 2, tig = lid & 3;
    const int b  = blockIdx.z;
    const int otile = blockIdx.y;
    const int o0 = otile * TILE_M;
    const int q0 = blockIdx.x * TILE_N;

    float acc[4][8][4];
    #pragma unroll
    for (int mi = 0; mi < 4; ++mi)
        #pragma unroll
        for (int ni = 0; ni < 8; ++ni)
            #pragma unroll
            for (int k = 0; k < 4; ++k) acc[mi][ni][k] = 0.f;

    load_stage(sb, 0, b, otile, q0, tid); cp_commit();
    load_stage(sb + STAGE_BYTES, 1, b, otile, q0, tid); cp_commit();

    int buf = 0;
    #pragma unroll 1
    for (int s = 0; s < NSTEPS; ++s) {
        cp_wait<1>();
        __syncthreads();
        if (s + 2 < NSTEPS) {
            int nb = (buf + 2 >= STAGES) ? buf + 2 - STAGES : buf + 2;
            load_stage(sb + nb*STAGE_BYTES, s + 2, b, otile, q0, tid);
        }
        cp_commit();

        const char* stA = smem + buf*STAGE_BYTES;
        const char* stB = stA + A_BYTES + (wn*64 + g)*B_PITCH + tig*8;
        #pragma unroll
        for (int kk = 0; kk < 2; ++kk) {
            uint4 a[4];
            uint2 bf[8];
            #pragma unroll
            for (int mi = 0; mi < 4; ++mi)
                a[mi] = *(const uint4*)(stA + ((kk*8 + wm*4 + mi)*32 + lid)*16);
            #pragma unroll
            for (int ni = 0; ni < 8; ++ni)
                bf[ni] = *(const uint2*)(stB + ni*8*B_PITCH + kk*32);
            #pragma unroll
            for (int mi = 0; mi < 4; ++mi)
                #pragma unroll
                for (int ni = 0; ni < 8; ++ni)
                    mma16(acc[mi][ni], a[mi], bf[ni]);
        }
        buf = (buf + 1 >= STAGES) ? 0 : buf + 1;
    }

    // ---------------- epilogue: BN + SiLU + guarded stores
    float inv[4][2], add[4][2];
    #pragma unroll
    for (int mi = 0; mi < 4; ++mi)
        #pragma unroll
        for (int hi = 0; hi < 2; ++hi) {
            int o = o0 + wm*64 + mi*16 + g + hi*8;
            float iv = gamma[o] * rsqrtf(var[o] + 1e-5f);
            inv[mi][hi] = iv;
            add[mi][hi] = beta[o] - mean[o] * iv;
        }
    #pragma unroll
    for (int mi = 0; mi < 4; ++mi) {
        #pragma unroll
        for (int ni = 0; ni < 8; ++ni) {
            #pragma unroll
            for (int k = 0; k < 4; ++k) {
                int hi = k >> 1, c = k & 1;
                int q = q0 + wn*64 + ni*8 + 2*tig + c;
                int hp = q / QP, wp = q - hp*QP;
                if (q < QN && hp >= 1 && hp <= NH && wp >= 1 && wp <= NW) {
                    int o = o0 + wm*64 + mi*16 + g + hi*8;
                    float z = acc[mi][ni][k] * inv[mi][hi] + add[mi][hi];
                    out[(((size_t)b*NC + o)*NH + hp - 1)*NW + wp - 1] =
                        z / (1.f + expf(-z));
                }
            }
        }
    }
}

// ------------------------------------------------------------------ launch
extern "C" void kernel_launch(void* const* d_in, const int* in_sizes, int n_in,
                              void* d_out, int out_size) {
    const float* x        = (const float*)d_in[0];
    const float* w_route  = (const float*)d_in[1];
    const float* b_route  = (const float*)d_in[2];
    const float* w_expert = (const float*)d_in[3];
    const float* bn_gamma = (const float*)d_in[4];
    const float* bn_beta  = (const float*)d_in[5];
    const float* bn_mean  = (const float*)d_in[6];
    const float* bn_var   = (const float*)d_in[7];
    float* out = (float*)d_out;

    cudaFuncSetAttribute(conv_mma_kernel,
                         cudaFuncAttributeMaxDynamicSharedMemorySize, SMEM_TOTAL);

    pool_kernel<<<NB*NC, 128>>>(x);
    route_kernel<<<1, 64>>>(w_route, b_route);
    fold_kernel<<<(NTAP*NC*NC + 255)/256, 256>>>(w_expert);
    dim3 xg(NC/64, QP, NB);
    xpad_kernel<<<xg, 256>>>(x);
    dim3 grid(QTILES, NC/TILE_M, NB);
    conv_mma_kernel<<<grid, 256, SMEM_TOTAL>>>(bn_gamma, bn_beta, bn_mean, bn_var, out);
}

// round 7
// speedup vs baseline: 1.0784x; 1.0784x over previous
#include <cuda_runtime.h>
#include <cuda_fp16.h>
#include <math.h>
#include <stdint.h>

#define NB 16
#define NC 256
#define NH 64
#define NW 64
#define NTAP 9
#define SEXP (NC*NC*NTAP)
#define QP 66
#define QN (QP*QP)                  /* 4356 padded pixels */
#define TILE_M 128
#define TILE_N 512
#define KC 32
#define NCHUNK 8
#define A_BYTES (TILE_M*KC*2)       /* 8192 per tile, fragment-major */
#define B_PITCH 80                  /* 64B data + 16B pad per pixel row */
#define B_ROWS 648                  /* 512 + 2*67 = 646, padded */
#define B_BYTES (B_ROWS*B_PITCH)    /* 51840 */
#define SMEM_TOTAL (2*A_BYTES + B_BYTES)  /* 68224 */
#define QTILES 9                    /* 9*512 = 4608 >= 4356 */

__device__ float g_pooled[NB*NC];
__device__ float g_routing[NB*4];
// A fp16 fragment-major: [b][t][otile(2)][chunk(8)][kk(2)][mblk(8)][lane(32)][reg(4)][e(2)]
__device__ __align__(1024) __half g_weff[(size_t)NB*NTAP*NC*NC];
// B fp16: [b][q][c_perm], perm within 16-group: pos = 4*tig + 2*khi + e
__device__ __align__(1024) __half g_xpad[(size_t)NB*QN*NC];

// ------------------------------------------------------------------ helpers
__device__ __forceinline__ uint32_t s2u(const void* p){
    uint32_t a;
    asm("{ .reg .u64 t; cvta.to.shared.u64 t, %1; cvt.u32.u64 %0, t; }" : "=r"(a) : "l"(p));
    return a;
}
__device__ __forceinline__ void cp16(uint32_t dst, const void* src, int szbytes){
    asm volatile("cp.async.cg.shared.global [%0], [%1], 16, %2;"
                 :: "r"(dst), "l"(src), "r"(szbytes) : "memory");
}
__device__ __forceinline__ void cp_commit(){
    asm volatile("cp.async.commit_group;" ::: "memory");
}
template<int N> __device__ __forceinline__ void cp_wait(){
    asm volatile("cp.async.wait_group %0;" :: "n"(N) : "memory");
}
__device__ __forceinline__ void mma16(float* d, const uint4 a, const uint2 b){
    asm volatile("mma.sync.aligned.m16n8k16.row.col.f32.f16.f16.f32 "
        "{%0,%1,%2,%3}, {%4,%5,%6,%7}, {%8,%9}, {%0,%1,%2,%3};"
        : "+f"(d[0]), "+f"(d[1]), "+f"(d[2]), "+f"(d[3])
        : "r"(a.x), "r"(a.y), "r"(a.z), "r"(a.w), "r"(b.x), "r"(b.y));
}

// ------------------------------------------------------------------ prep
__global__ void pool_kernel(const float* __restrict__ x) {
    int bc = blockIdx.x;
    const float4* p = (const float4*)(x + (size_t)bc * NH * NW);
    float s = 0.f;
    for (int i = threadIdx.x; i < NH*NW/4; i += blockDim.x) {
        float4 v = p[i];
        s += v.x + v.y + v.z + v.w;
    }
    #pragma unroll
    for (int o = 16; o; o >>= 1) s += __shfl_xor_sync(0xffffffffu, s, o);
    __shared__ float red[4];
    if ((threadIdx.x & 31) == 0) red[threadIdx.x >> 5] = s;
    __syncthreads();
    if (threadIdx.x == 0)
        g_pooled[bc] = (red[0]+red[1]+red[2]+red[3]) * (1.0f/(NH*NW));
}

__global__ void route_kernel(const float* __restrict__ wr, const float* __restrict__ br) {
    int t = threadIdx.x;
    if (t >= NB*4) return;
    int b = t >> 2, e = t & 3;
    float acc = br[e];
    const float* pw = wr + e*NC;
    const float* pp = g_pooled + b*NC;
    #pragma unroll 8
    for (int c = 0; c < NC; ++c) acc = fmaf(pp[c], pw[c], acc);
    g_routing[t] = 1.f/(1.f + expf(-acc));
}

// Destination-coalesced fold: thread = dst fragment element, invert mapping.
__global__ void fold_kernel(const float* __restrict__ we) {
    int lin = blockIdx.x * blockDim.x + threadIdx.x;   // 0 .. 589823
    int inner = lin & 4095;
    int chunk = (lin >> 12) & 7;
    int otile = (lin >> 15) & 1;
    int t     = lin >> 16;
    // invert fragment mapping
    int e    = inner & 1;
    int reg  = (inner >> 1) & 3;
    int lane = (inner >> 3) & 31;
    int mblk = (inner >> 8) & 7;
    int kk   = inner >> 11;
    int tig = lane & 3, g8 = lane >> 2;
    int khi = reg >> 1, ohi = reg & 1;
    int o = otile*128 + mblk*16 + ohi*8 + g8;
    int c = chunk*32 + kk*16 + khi*8 + tig*2 + e;

    size_t wi = ((size_t)o*NC + c)*NTAP + t;
    float w0 = we[wi], w1 = we[wi + (size_t)SEXP];
    float w2 = we[wi + 2*(size_t)SEXP], w3 = we[wi + 3*(size_t)SEXP];
    #pragma unroll
    for (int b = 0; b < NB; ++b) {
        const float* r = g_routing + b*4;
        g_weff[(size_t)b*(NTAP*NC*NC) + lin] =
            __float2half_rn(w0*r[0] + w1*r[1] + w2*r[2] + w3*r[3]);
    }
}

// x_pad[b][q][c_perm] fp16, q over 66x66 grid, zero ring.
__global__ void xpad_kernel(const float* __restrict__ x) {
    __shared__ float s[64*65];
    int c0 = blockIdx.x * 64, hp = blockIdx.y, b = blockIdx.z;
    int h = hp - 1;
    bool hv = (h >= 0 && h < NH);
    if (hv) {
        const float* xp = x + ((size_t)(b*NC + c0))*(NH*NW) + (size_t)h*NW;
        for (int j = 0; j < 16; ++j) {
            int idx = j*256 + threadIdx.x;
            int i = idx >> 6, w = idx & 63;
            s[w*65 + i] = xp[(size_t)i*(NH*NW) + w];
        }
    }
    __syncthreads();
    __half* op = g_xpad + ((size_t)b*QN + (size_t)hp*QP)*NC + c0;
    for (int j = 0; j < 17; ++j) {
        int idx = j*256 + threadIdx.x;
        if (idx >= QP*64) break;
        int i = idx & 63, wp = idx >> 6;
        float v = 0.f;
        if (hv && wp >= 1 && wp <= 64) v = s[(wp-1)*65 + i];
        int kc = i & 15;
        int ipos = (i & ~15) | (4*((kc & 7) >> 1) + 2*(kc >> 3) + (kc & 1));
        op[(size_t)wp*NC + ipos] = __float2half_rn(v);
    }
}

// ------------------------------------------------------------------ conv GEMM
// smem layout: [A buf0 8KB][A buf1 8KB][B block 648*80]
__global__ void __launch_bounds__(512, 1)
conv_mma_kernel(const float* __restrict__ gamma, const float* __restrict__ beta,
                const float* __restrict__ mean,  const float* __restrict__ var,
                float* __restrict__ out)
{
    extern __shared__ __align__(128) char smem[];
    const uint32_t sb = s2u(smem);
    const uint32_t sbB = sb + 2*A_BYTES;
    const int tid = threadIdx.x, wid = tid >> 5, lid = tid & 31;
    const int wm = wid >> 3, wn = wid & 7;        // warp grid 2 (M) x 8 (N)
    const int g = lid >> 2, tig = lid & 3;
    const int b  = blockIdx.z;
    const int otile = blockIdx.y;
    const int o0 = otile * TILE_M;
    const int q0 = blockIdx.x * TILE_N;

    const __half* bG = g_xpad + (size_t)b*QN*NC;
    const __half* aGbase = g_weff + (size_t)b*(NTAP*NC*NC);

    float acc[4][8][4];
    #pragma unroll
    for (int mi = 0; mi < 4; ++mi)
        #pragma unroll
        for (int ni = 0; ni < 8; ++ni)
            #pragma unroll
            for (int k = 0; k < 4; ++k) acc[mi][ni][k] = 0.f;

    #pragma unroll 1
    for (int chunk = 0; chunk < NCHUNK; ++chunk) {
        __syncthreads();   // previous chunk fully consumed (B + A buf0)
        // ---- load B block (once per chunk): rows q0-67 .. q0+578
        {
            const __half* bC = bG + chunk*KC;
            #pragma unroll
            for (int jj = 0; jj < 6; ++jj) {
                int seg = tid + jj*512;
                if (seg < 646*4) {
                    int row = seg >> 2, j = seg & 3;
                    int q = q0 - 67 + row;
                    bool v = ((unsigned)q < (unsigned)QN);
                    const __half* src = bC + (size_t)(v ? q : 0)*NC + j*8;
                    cp16(sbB + row*B_PITCH + j*16, src, v ? 16 : 0);
                }
            }
        }
        // ---- load A(t=0) into buf 0
        {
            const __half* aG = aGbase + ((((size_t)0*2 + otile)*8 + chunk)*4096);
            cp16(sb + tid*16, aG + tid*8, 16);
        }
        cp_commit();

        #pragma unroll 1
        for (int t = 0; t < NTAP; ++t) {
            int abuf = t & 1;
            if (t + 1 < NTAP) {
                const __half* aG = aGbase + ((((size_t)(t+1)*2 + otile)*8 + chunk)*4096);
                cp16(sb + (abuf^1)*A_BYTES + tid*16, aG + tid*8, 16);
            }
            cp_commit();
            cp_wait<1>();
            __syncthreads();

            int dh = t / 3, dw = t - dh*3;
            int shift = (dh-1)*QP + (dw-1);
            uint32_t stA = sb + abuf*A_BYTES;
            uint32_t stBr = sbB + (67 + shift + wn*64 + g)*B_PITCH + tig*8;
            #pragma unroll
            for (int kk = 0; kk < 2; ++kk) {
                uint4 a[4];
                uint2 bf[8];
                #pragma unroll
                for (int mi = 0; mi < 4; ++mi)
                    a[mi] = *(const uint4*)(smem + (stA - sb) + ((kk*8 + wm*4 + mi)*32 + lid)*16);
                #pragma unroll
                for (int ni = 0; ni < 8; ++ni)
                    bf[ni] = *(const uint2*)(smem + (stBr - sb) + ni*8*B_PITCH + kk*32);
                #pragma unroll
                for (int mi = 0; mi < 4; ++mi)
                    #pragma unroll
                    for (int ni = 0; ni < 8; ++ni)
                        mma16(acc[mi][ni], a[mi], bf[ni]);
            }
            __syncthreads();   // all warps done with A(abuf) before overwrite next t
        }
    }

    // ---------------- epilogue: BN + SiLU + guarded stores
    float inv[4][2], add[4][2];
    #pragma unroll
    for (int mi = 0; mi < 4; ++mi)
        #pragma unroll
        for (int hi = 0; hi < 2; ++hi) {
            int o = o0 + wm*64 + mi*16 + g + hi*8;
            float iv = gamma[o] * rsqrtf(var[o] + 1e-5f);
            inv[mi][hi] = iv;
            add[mi][hi] = beta[o] - mean[o] * iv;
        }
    #pragma unroll
    for (int mi = 0; mi < 4; ++mi) {
        #pragma unroll
        for (int ni = 0; ni < 8; ++ni) {
            #pragma unroll
            for (int k = 0; k < 4; ++k) {
                int hi = k >> 1, c = k & 1;
                int q = q0 + wn*64 + ni*8 + 2*tig + c;
                int hp = q / QP, wp = q - hp*QP;
                if (q < QN && hp >= 1 && hp <= NH && wp >= 1 && wp <= NW) {
                    int o = o0 + wm*64 + mi*16 + g + hi*8;
                    float z = acc[mi][ni][k] * inv[mi][hi] + add[mi][hi];
                    out[(((size_t)b*NC + o)*NH + hp - 1)*NW + wp - 1] =
                        z / (1.f + expf(-z));
                }
            }
        }
    }
}

// ------------------------------------------------------------------ launch
extern "C" void kernel_launch(void* const* d_in, const int* in_sizes, int n_in,
                              void* d_out, int out_size) {
    const float* x        = (const float*)d_in[0];
    const float* w_route  = (const float*)d_in[1];
    const float* b_route  = (const float*)d_in[2];
    const float* w_expert = (const float*)d_in[3];
    const float* bn_gamma = (const float*)d_in[4];
    const float* bn_beta  = (const float*)d_in[5];
    const float* bn_mean  = (const float*)d_in[6];
    const float* bn_var   = (const float*)d_in[7];
    float* out = (float*)d_out;

    cudaFuncSetAttribute(conv_mma_kernel,
                         cudaFuncAttributeMaxDynamicSharedMemorySize, SMEM_TOTAL);

    pool_kernel<<<NB*NC, 128>>>(x);
    route_kernel<<<1, 64>>>(w_route, b_route);
    fold_kernel<<<(NTAP*2*NCHUNK*4096)/256, 256>>>(w_expert);
    dim3 xg(NC/64, QP, NB);
    xpad_kernel<<<xg, 256>>>(x);
    dim3 grid(QTILES, NC/TILE_M, NB);
    conv_mma_kernel<<<grid, 512, SMEM_TOTAL>>>(bn_gamma, bn_beta, bn_mean, bn_var, out);
}

// round 8
// speedup vs baseline: 2.0679x; 1.9175x over previous
#include <cuda_runtime.h>
#include <cuda_fp16.h>
#include <math.h>
#include <stdint.h>

#define NB 16
#define NC 256
#define NH 64
#define NW 64
#define NTAP 9
#define SEXP (NC*NC*NTAP)
#define QP 66
#define QN (QP*QP)                  /* 4356 padded pixels */
#define TILE_M 128
#define TILE_N 256
#define KC 32
#define NCHUNK 8
#define A_TAP_BYTES 8192            /* 128 rows x 32 ch fp16, fragment-major */
#define A_CHUNK_BYTES (NTAP*A_TAP_BYTES)   /* 73728 */
#define B_PITCH 96                  /* 64B data + 32B pad: conflict-free LDS.64 */
#define B_ROWS 392                  /* 256 + 2*67 = 390, padded */
#define B_BYTES (B_ROWS*B_PITCH)    /* 37632 */
#define SMEM_TOTAL (2*A_CHUNK_BYTES + B_BYTES)  /* 185088 */
#define QTILES 18                   /* ceil(4356/256) */

__device__ float g_pooled[NB*NC];
__device__ float g_routing[NB*4];
// A fp16 fragment-major: [b][otile(2)][chunk(8)][t(9)][inner 4096]
// inner = ((kk*8+mblk)*32 + lane)*8 + reg*2 + e   (m16n8k16 A fragment)
__device__ __align__(1024) __half g_weff[(size_t)NB*NTAP*NC*NC];
// B fp16: [b][q][c_perm], perm within 16-group: pos = 4*tig + 2*khi + e
__device__ __align__(1024) __half g_xpad[(size_t)NB*QN*NC];

// ------------------------------------------------------------------ helpers
__device__ __forceinline__ uint32_t s2u(const void* p){
    uint32_t a;
    asm("{ .reg .u64 t; cvta.to.shared.u64 t, %1; cvt.u32.u64 %0, t; }" : "=r"(a) : "l"(p));
    return a;
}
__device__ __forceinline__ void cp16(uint32_t dst, const void* src, int szbytes){
    asm volatile("cp.async.cg.shared.global [%0], [%1], 16, %2;"
                 :: "r"(dst), "l"(src), "r"(szbytes) : "memory");
}
__device__ __forceinline__ void cp_commit(){
    asm volatile("cp.async.commit_group;" ::: "memory");
}
template<int N> __device__ __forceinline__ void cp_wait(){
    asm volatile("cp.async.wait_group %0;" :: "n"(N) : "memory");
}
__device__ __forceinline__ void mma16(float* d, const uint4 a, const uint2 b){
    asm volatile("mma.sync.aligned.m16n8k16.row.col.f32.f16.f16.f32 "
        "{%0,%1,%2,%3}, {%4,%5,%6,%7}, {%8,%9}, {%0,%1,%2,%3};"
        : "+f"(d[0]), "+f"(d[1]), "+f"(d[2]), "+f"(d[3])
        : "r"(a.x), "r"(a.y), "r"(a.z), "r"(a.w), "r"(b.x), "r"(b.y));
}

// ------------------------------------------------------------------ prep
__global__ void pool_kernel(const float* __restrict__ x) {
    int bc = blockIdx.x;
    const float4* p = (const float4*)(x + (size_t)bc * NH * NW);
    float s = 0.f;
    for (int i = threadIdx.x; i < NH*NW/4; i += blockDim.x) {
        float4 v = p[i];
        s += v.x + v.y + v.z + v.w;
    }
    #pragma unroll
    for (int o = 16; o; o >>= 1) s += __shfl_xor_sync(0xffffffffu, s, o);
    __shared__ float red[4];
    if ((threadIdx.x & 31) == 0) red[threadIdx.x >> 5] = s;
    __syncthreads();
    if (threadIdx.x == 0)
        g_pooled[bc] = (red[0]+red[1]+red[2]+red[3]) * (1.0f/(NH*NW));
}

__global__ void route_kernel(const float* __restrict__ wr, const float* __restrict__ br) {
    int t = threadIdx.x;
    if (t >= NB*4) return;
    int b = t >> 2, e = t & 3;
    float acc = br[e];
    const float* pw = wr + e*NC;
    const float* pp = g_pooled + b*NC;
    #pragma unroll 8
    for (int c = 0; c < NC; ++c) acc = fmaf(pp[c], pw[c], acc);
    g_routing[t] = 1.f/(1.f + expf(-acc));
}

// Destination-coalesced fold into [otile][chunk][t][inner] layout.
__global__ void fold_kernel(const float* __restrict__ we) {
    int lin = blockIdx.x * blockDim.x + threadIdx.x;   // 0 .. 589823
    int inner = lin & 4095;
    int rest  = lin >> 12;          // 0..143
    int t     = rest % 9;
    int oc    = rest / 9;           // 0..15
    int chunk = oc & 7;
    int otile = oc >> 3;
    // invert fragment mapping
    int e    = inner & 1;
    int reg  = (inner >> 1) & 3;
    int lane = (inner >> 3) & 31;
    int mblk = (inner >> 8) & 7;
    int kk   = inner >> 11;
    int tig = lane & 3, g8 = lane >> 2;
    int khi = reg >> 1, ohi = reg & 1;
    int o = otile*128 + mblk*16 + ohi*8 + g8;
    int c = chunk*32 + kk*16 + khi*8 + tig*2 + e;

    size_t wi = ((size_t)o*NC + c)*NTAP + t;
    float w0 = we[wi], w1 = we[wi + (size_t)SEXP];
    float w2 = we[wi + 2*(size_t)SEXP], w3 = we[wi + 3*(size_t)SEXP];
    #pragma unroll
    for (int b = 0; b < NB; ++b) {
        const float* r = g_routing + b*4;
        g_weff[(size_t)b*(NTAP*NC*NC) + lin] =
            __float2half_rn(w0*r[0] + w1*r[1] + w2*r[2] + w3*r[3]);
    }
}

// x_pad[b][q][c_perm] fp16, q over 66x66 grid, zero ring.
__global__ void xpad_kernel(const float* __restrict__ x) {
    __shared__ float s[64*65];
    int c0 = blockIdx.x * 64, hp = blockIdx.y, b = blockIdx.z;
    int h = hp - 1;
    bool hv = (h >= 0 && h < NH);
    if (hv) {
        const float* xp = x + ((size_t)(b*NC + c0))*(NH*NW) + (size_t)h*NW;
        for (int j = 0; j < 16; ++j) {
            int idx = j*256 + threadIdx.x;
            int i = idx >> 6, w = idx & 63;
            s[w*65 + i] = xp[(size_t)i*(NH*NW) + w];
        }
    }
    __syncthreads();
    __half* op = g_xpad + ((size_t)b*QN + (size_t)hp*QP)*NC + c0;
    for (int j = 0; j < 17; ++j) {
        int idx = j*256 + threadIdx.x;
        if (idx >= QP*64) break;
        int i = idx & 63, wp = idx >> 6;
        float v = 0.f;
        if (hv && wp >= 1 && wp <= 64) v = s[(wp-1)*65 + i];
        int kc = i & 15;
        int ipos = (i & ~15) | (4*((kc & 7) >> 1) + 2*(kc >> 3) + (kc & 1));
        op[(size_t)wp*NC + ipos] = __float2half_rn(v);
    }
}

// ------------------------------------------------------------------ conv GEMM
// smem: [A buf0 72KB][A buf1 72KB][B block 392*96]
__global__ void __launch_bounds__(256, 1)
conv_mma_kernel(const float* __restrict__ gamma, const float* __restrict__ beta,
                const float* __restrict__ mean,  const float* __restrict__ var,
                float* __restrict__ out)
{
    extern __shared__ __align__(128) char smem[];
    const uint32_t sb = s2u(smem);
    const uint32_t sbB = sb + 2*A_CHUNK_BYTES;
    const int tid = threadIdx.x, wid = tid >> 5, lid = tid & 31;
    const int wm = wid >> 2, wn = wid & 3;        // warp grid 2 (M) x 4 (N)
    const int g = lid >> 2, tig = lid & 3;
    const int b  = blockIdx.z;
    const int otile = blockIdx.y;
    const int o0 = otile * TILE_M;
    const int q0 = blockIdx.x * TILE_N;

    const __half* bG = g_xpad + (size_t)b*QN*NC;
    // A source for chunk c: one contiguous 72KB region
    const __half* aGbase = g_weff + (size_t)b*(NTAP*NC*NC)
                         + (size_t)otile*(8*NTAP*4096);

    float acc[4][8][4];
    #pragma unroll
    for (int mi = 0; mi < 4; ++mi)
        #pragma unroll
        for (int ni = 0; ni < 8; ++ni)
            #pragma unroll
            for (int k = 0; k < 4; ++k) acc[mi][ni][k] = 0.f;

    // prologue: A(chunk 0) -> buf 0
    {
        const __half* aG = aGbase;           // chunk 0
        #pragma unroll
        for (int j = 0; j < 18; ++j) {
            int seg = tid + j*256;
            cp16(sb + seg*16, aG + (size_t)seg*8, 16);
        }
        cp_commit();
    }

    #pragma unroll 1
    for (int chunk = 0; chunk < NCHUNK; ++chunk) {
        __syncthreads();   // prev chunk's B + this chunk's A-buf fully consumed
        // ---- B block for this chunk (single-buffered)
        {
            const __half* bC = bG + chunk*KC;
            #pragma unroll
            for (int jj = 0; jj < 7; ++jj) {
                int seg = tid + jj*256;
                if (seg < 390*4) {
                    int row = seg >> 2, j = seg & 3;
                    int q = q0 - 67 + row;
                    bool v = ((unsigned)q < (unsigned)QN);
                    const __half* src = bC + (size_t)(v ? q : 0)*NC + j*8;
                    cp16(sbB + row*B_PITCH + j*16, src, v ? 16 : 0);
                }
            }
            cp_commit();
        }
        // ---- prefetch A(chunk+1) into other buffer
        if (chunk + 1 < NCHUNK) {
            const __half* aG = aGbase + (size_t)(chunk+1)*(NTAP*4096);
            uint32_t dst = sb + ((chunk+1) & 1)*A_CHUNK_BYTES;
            #pragma unroll
            for (int j = 0; j < 18; ++j) {
                int seg = tid + j*256;
                cp16(dst + seg*16, aG + (size_t)seg*8, 16);
            }
        }
        cp_commit();
        cp_wait<1>();      // A(chunk) and B(chunk) complete; A(chunk+1) may fly
        __syncthreads();

        const char* aBuf = smem + (chunk & 1)*A_CHUNK_BYTES;
        const char* bBase = smem + 2*A_CHUNK_BYTES;
        #pragma unroll 1
        for (int t = 0; t < NTAP; ++t) {
            int dh = t / 3, dw = t - dh*3;
            int shift = (dh-1)*QP + (dw-1);
            const char* aT = aBuf + t*A_TAP_BYTES;
            const char* bW = bBase + (67 + shift + wn*64 + g)*B_PITCH + tig*8;
            #pragma unroll
            for (int kk = 0; kk < 2; ++kk) {
                uint4 a[4];
                uint2 bf[8];
                #pragma unroll
                for (int mi = 0; mi < 4; ++mi)
                    a[mi] = *(const uint4*)(aT + ((kk*8 + wm*4 + mi)*32 + lid)*16);
                #pragma unroll
                for (int ni = 0; ni < 8; ++ni)
                    bf[ni] = *(const uint2*)(bW + ni*8*B_PITCH + kk*32);
                #pragma unroll
                for (int mi = 0; mi < 4; ++mi)
                    #pragma unroll
                    for (int ni = 0; ni < 8; ++ni)
                        mma16(acc[mi][ni], a[mi], bf[ni]);
            }
        }
    }

    // ---------------- epilogue: BN + SiLU + guarded stores
    float inv[4][2], add[4][2];
    #pragma unroll
    for (int mi = 0; mi < 4; ++mi)
        #pragma unroll
        for (int hi = 0; hi < 2; ++hi) {
            int o = o0 + wm*64 + mi*16 + g + hi*8;
            float iv = gamma[o] * rsqrtf(var[o] + 1e-5f);
            inv[mi][hi] = iv;
            add[mi][hi] = beta[o] - mean[o] * iv;
        }
    #pragma unroll
    for (int mi = 0; mi < 4; ++mi) {
        #pragma unroll
        for (int ni = 0; ni < 8; ++ni) {
            #pragma unroll
            for (int k = 0; k < 4; ++k) {
                int hi = k >> 1, c = k & 1;
                int q = q0 + wn*64 + ni*8 + 2*tig + c;
                int hp = q / QP, wp = q - hp*QP;
                if (q < QN && hp >= 1 && hp <= NH && wp >= 1 && wp <= NW) {
                    int o = o0 + wm*64 + mi*16 + g + hi*8;
                    float z = acc[mi][ni][k] * inv[mi][hi] + add[mi][hi];
                    out[(((size_t)b*NC + o)*NH + hp - 1)*NW + wp - 1] =
                        z / (1.f + expf(-z));
                }
            }
        }
    }
}

// ------------------------------------------------------------------ launch
extern "C" void kernel_launch(void* const* d_in, const int* in_sizes, int n_in,
                              void* d_out, int out_size) {
    const float* x        = (const float*)d_in[0];
    const float* w_route  = (const float*)d_in[1];
    const float* b_route  = (const float*)d_in[2];
    const float* w_expert = (const float*)d_in[3];
    const float* bn_gamma = (const float*)d_in[4];
    const float* bn_beta  = (const float*)d_in[5];
    const float* bn_mean  = (const float*)d_in[6];
    const float* bn_var   = (const float*)d_in[7];
    float* out = (float*)d_out;

    cudaFuncSetAttribute(conv_mma_kernel,
                         cudaFuncAttributeMaxDynamicSharedMemorySize, SMEM_TOTAL);

    pool_kernel<<<NB*NC, 128>>>(x);
    route_kernel<<<1, 64>>>(w_route, b_route);
    fold_kernel<<<SEXP/256, 256>>>(w_expert);
    dim3 xg(NC/64, QP, NB);
    xpad_kernel<<<xg, 256>>>(x);
    dim3 grid(QTILES, NC/TILE_M, NB);
    conv_mma_kernel<<<grid, 256, SMEM_TOTAL>>>(bn_gamma, bn_beta, bn_mean, bn_var, out);
}

// round 9
// speedup vs baseline: 2.0953x; 1.0132x over previous
#include <cuda_runtime.h>
#include <cuda_fp16.h>
#include <math.h>
#include <stdint.h>

#define NB 16
#define NC 256
#define NH 64
#define NW 64
#define NTAP 9
#define SEXP (NC*NC*NTAP)
#define QP 66
#define QN (QP*QP)                  /* 4356 padded pixels */
#define TILE_M 128
#define TILE_N 256
#define KC 32
#define NCHUNK 8
#define A_TAP_BYTES 8192            /* 128 rows x 32 ch fp16, fragment-major */
#define A_CHUNK_BYTES (NTAP*A_TAP_BYTES)   /* 73728 */
#define B_PITCH 96                  /* 64B data + 32B pad: conflict-free LDS.64 */
#define B_ROWS 392                  /* 256 + 2*67 = 390, padded */
#define B_BYTES (B_ROWS*B_PITCH)    /* 37632 */
#define SMEM_TOTAL (2*A_CHUNK_BYTES + 2*B_BYTES)  /* 222720 */
#define QTILES 18                   /* ceil(4356/256) */

__device__ float g_pooled[NB*NC];
__device__ float g_routing[NB*4];
// A fp16 fragment-major: [b][otile(2)][chunk(8)][t(9)][inner 4096]
// inner = ((kk*8+mblk)*32 + lane)*8 + reg*2 + e   (m16n8k16 A fragment)
__device__ __align__(1024) __half g_weff[(size_t)NB*NTAP*NC*NC];
// B fp16: [b][q][c_perm], perm within 16-group: pos = 4*tig + 2*khi + e
__device__ __align__(1024) __half g_xpad[(size_t)NB*QN*NC];

// ------------------------------------------------------------------ helpers
__device__ __forceinline__ uint32_t s2u(const void* p){
    uint32_t a;
    asm("{ .reg .u64 t; cvta.to.shared.u64 t, %1; cvt.u32.u64 %0, t; }" : "=r"(a) : "l"(p));
    return a;
}
__device__ __forceinline__ void cp16(uint32_t dst, const void* src, int szbytes){
    asm volatile("cp.async.cg.shared.global [%0], [%1], 16, %2;"
                 :: "r"(dst), "l"(src), "r"(szbytes) : "memory");
}
__device__ __forceinline__ void cp_commit(){
    asm volatile("cp.async.commit_group;" ::: "memory");
}
template<int N> __device__ __forceinline__ void cp_wait(){
    asm volatile("cp.async.wait_group %0;" :: "n"(N) : "memory");
}
__device__ __forceinline__ void mma16(float* d, const uint4 a, const uint2 b){
    asm volatile("mma.sync.aligned.m16n8k16.row.col.f32.f16.f16.f32 "
        "{%0,%1,%2,%3}, {%4,%5,%6,%7}, {%8,%9}, {%0,%1,%2,%3};"
        : "+f"(d[0]), "+f"(d[1]), "+f"(d[2]), "+f"(d[3])
        : "r"(a.x), "r"(a.y), "r"(a.z), "r"(a.w), "r"(b.x), "r"(b.y));
}

// ------------------------------------------------------------------ prep
__global__ void pool_kernel(const float* __restrict__ x) {
    int bc = blockIdx.x;
    const float4* p = (const float4*)(x + (size_t)bc * NH * NW);
    float s = 0.f;
    for (int i = threadIdx.x; i < NH*NW/4; i += blockDim.x) {
        float4 v = p[i];
        s += v.x + v.y + v.z + v.w;
    }
    #pragma unroll
    for (int o = 16; o; o >>= 1) s += __shfl_xor_sync(0xffffffffu, s, o);
    __shared__ float red[4];
    if ((threadIdx.x & 31) == 0) red[threadIdx.x >> 5] = s;
    __syncthreads();
    if (threadIdx.x == 0)
        g_pooled[bc] = (red[0]+red[1]+red[2]+red[3]) * (1.0f/(NH*NW));
}

__global__ void route_kernel(const float* __restrict__ wr, const float* __restrict__ br) {
    int t = threadIdx.x;
    if (t >= NB*4) return;
    int b = t >> 2, e = t & 3;
    float acc = br[e];
    const float* pw = wr + e*NC;
    const float* pp = g_pooled + b*NC;
    #pragma unroll 8
    for (int c = 0; c < NC; ++c) acc = fmaf(pp[c], pw[c], acc);
    g_routing[t] = 1.f/(1.f + expf(-acc));
}

// Destination-coalesced fold into [otile][chunk][t][inner] layout.
__global__ void fold_kernel(const float* __restrict__ we) {
    int lin = blockIdx.x * blockDim.x + threadIdx.x;   // 0 .. 589823
    int inner = lin & 4095;
    int rest  = lin >> 12;          // 0..143
    int t     = rest % 9;
    int oc    = rest / 9;           // 0..15
    int chunk = oc & 7;
    int otile = oc >> 3;
    // invert fragment mapping
    int e    = inner & 1;
    int reg  = (inner >> 1) & 3;
    int lane = (inner >> 3) & 31;
    int mblk = (inner >> 8) & 7;
    int kk   = inner >> 11;
    int tig = lane & 3, g8 = lane >> 2;
    int khi = reg >> 1, ohi = reg & 1;
    int o = otile*128 + mblk*16 + ohi*8 + g8;
    int c = chunk*32 + kk*16 + khi*8 + tig*2 + e;

    size_t wi = ((size_t)o*NC + c)*NTAP + t;
    float w0 = we[wi], w1 = we[wi + (size_t)SEXP];
    float w2 = we[wi + 2*(size_t)SEXP], w3 = we[wi + 3*(size_t)SEXP];
    #pragma unroll
    for (int b = 0; b < NB; ++b) {
        const float* r = g_routing + b*4;
        g_weff[(size_t)b*(NTAP*NC*NC) + lin] =
            __float2half_rn(w0*r[0] + w1*r[1] + w2*r[2] + w3*r[3]);
    }
}

// x_pad[b][q][c_perm] fp16, q over 66x66 grid, zero ring.
__global__ void xpad_kernel(const float* __restrict__ x) {
    __shared__ float s[64*65];
    int c0 = blockIdx.x * 64, hp = blockIdx.y, b = blockIdx.z;
    int h = hp - 1;
    bool hv = (h >= 0 && h < NH);
    if (hv) {
        const float* xp = x + ((size_t)(b*NC + c0))*(NH*NW) + (size_t)h*NW;
        for (int j = 0; j < 16; ++j) {
            int idx = j*256 + threadIdx.x;
            int i = idx >> 6, w = idx & 63;
            s[w*65 + i] = xp[(size_t)i*(NH*NW) + w];
        }
    }
    __syncthreads();
    __half* op = g_xpad + ((size_t)b*QN + (size_t)hp*QP)*NC + c0;
    for (int j = 0; j < 17; ++j) {
        int idx = j*256 + threadIdx.x;
        if (idx >= QP*64) break;
        int i = idx & 63, wp = idx >> 6;
        float v = 0.f;
        if (hv && wp >= 1 && wp <= 64) v = s[(wp-1)*65 + i];
        int kc = i & 15;
        int ipos = (i & ~15) | (4*((kc & 7) >> 1) + 2*(kc >> 3) + (kc & 1));
        op[(size_t)wp*NC + ipos] = __float2half_rn(v);
    }
}

// ------------------------------------------------------------------ conv GEMM
// smem: [A buf0 72KB][A buf1 72KB][B buf0 36.75KB][B buf1 36.75KB]
__device__ __forceinline__ void load_chunk(uint32_t sb, int chunk, int q0,
                                           const __half* aGbase, const __half* bG,
                                           int tid)
{
    int bufsel = chunk & 1;
    // A: 72KB linear
    const __half* aG = aGbase + (size_t)chunk*(NTAP*4096);
    uint32_t aDst = sb + bufsel*A_CHUNK_BYTES;
    #pragma unroll
    for (int j = 0; j < 18; ++j) {
        int seg = tid + j*256;
        cp16(aDst + seg*16, aG + (size_t)seg*8, 16);
    }
    // B: rows q0-67 .. q0+322
    const __half* bC = bG + chunk*KC;
    uint32_t bDst = sb + 2*A_CHUNK_BYTES + bufsel*B_BYTES;
    #pragma unroll
    for (int jj = 0; jj < 7; ++jj) {
        int seg = tid + jj*256;
        if (seg < 390*4) {
            int row = seg >> 2, j = seg & 3;
            int q = q0 - 67 + row;
            bool v = ((unsigned)q < (unsigned)QN);
            const __half* src = bC + (size_t)(v ? q : 0)*NC + j*8;
            cp16(bDst + row*B_PITCH + j*16, src, v ? 16 : 0);
        }
    }
}

__global__ void __launch_bounds__(256, 1)
conv_mma_kernel(const float* __restrict__ gamma, const float* __restrict__ beta,
                const float* __restrict__ mean,  const float* __restrict__ var,
                float* __restrict__ out)
{
    extern __shared__ __align__(128) char smem[];
    const uint32_t sb = s2u(smem);
    const int tid = threadIdx.x, wid = tid >> 5, lid = tid & 31;
    const int wm = wid >> 2, wn = wid & 3;        // warp grid 2 (M) x 4 (N)
    const int g = lid >> 2, tig = lid & 3;
    const int b  = blockIdx.z;
    const int otile = blockIdx.y;
    const int o0 = otile * TILE_M;
    const int q0 = blockIdx.x * TILE_N;

    const __half* bG = g_xpad + (size_t)b*QN*NC;
    const __half* aGbase = g_weff + (size_t)b*(NTAP*NC*NC)
                         + (size_t)otile*(8*NTAP*4096);

    float acc[4][8][4];
    #pragma unroll
    for (int mi = 0; mi < 4; ++mi)
        #pragma unroll
        for (int ni = 0; ni < 8; ++ni)
            #pragma unroll
            for (int k = 0; k < 4; ++k) acc[mi][ni][k] = 0.f;

    // prologue: chunk 0 -> buffers 0
    load_chunk(sb, 0, q0, aGbase, bG, tid);
    cp_commit();

    #pragma unroll 1
    for (int chunk = 0; chunk < NCHUNK; ++chunk) {
        __syncthreads();   // all warps finished reading buffers[(chunk+1)&1]
        if (chunk + 1 < NCHUNK)
            load_chunk(sb, chunk + 1, q0, aGbase, bG, tid);
        cp_commit();
        cp_wait<1>();      // chunk's own data complete (arrived during prev compute)
        __syncthreads();

        const char* aBuf = smem + (chunk & 1)*A_CHUNK_BYTES;
        const char* bBase = smem + 2*A_CHUNK_BYTES + (chunk & 1)*B_BYTES;
        #pragma unroll 1
        for (int t = 0; t < NTAP; ++t) {
            int dh = t / 3, dw = t - dh*3;
            int shift = (dh-1)*QP + (dw-1);
            const char* aT = aBuf + t*A_TAP_BYTES;
            const char* bW = bBase + (67 + shift + wn*64 + g)*B_PITCH + tig*8;
            #pragma unroll
            for (int kk = 0; kk < 2; ++kk) {
                uint4 a[4];
                uint2 bf[8];
                #pragma unroll
                for (int mi = 0; mi < 4; ++mi)
                    a[mi] = *(const uint4*)(aT + ((kk*8 + wm*4 + mi)*32 + lid)*16);
                #pragma unroll
                for (int ni = 0; ni < 8; ++ni)
                    bf[ni] = *(const uint2*)(bW + ni*8*B_PITCH + kk*32);
                #pragma unroll
                for (int mi = 0; mi < 4; ++mi)
                    #pragma unroll
                    for (int ni = 0; ni < 8; ++ni)
                        mma16(acc[mi][ni], a[mi], bf[ni]);
            }
        }
    }

    // ---------------- epilogue: BN + SiLU + guarded stores
    float inv[4][2], add[4][2];
    #pragma unroll
    for (int mi = 0; mi < 4; ++mi)
        #pragma unroll
        for (int hi = 0; hi < 2; ++hi) {
            int o = o0 + wm*64 + mi*16 + g + hi*8;
            float iv = gamma[o] * rsqrtf(var[o] + 1e-5f);
            inv[mi][hi] = iv;
            add[mi][hi] = beta[o] - mean[o] * iv;
        }
    #pragma unroll
    for (int mi = 0; mi < 4; ++mi) {
        #pragma unroll
        for (int ni = 0; ni < 8; ++ni) {
            #pragma unroll
            for (int k = 0; k < 4; ++k) {
                int hi = k >> 1, c = k & 1;
                int q = q0 + wn*64 + ni*8 + 2*tig + c;
                int hp = q / QP, wp = q - hp*QP;
                if (q < QN && hp >= 1 && hp <= NH && wp >= 1 && wp <= NW) {
                    int o = o0 + wm*64 + mi*16 + g + hi*8;
                    float z = acc[mi][ni][k] * inv[mi][hi] + add[mi][hi];
                    out[(((size_t)b*NC + o)*NH + hp - 1)*NW + wp - 1] =
                        z / (1.f + expf(-z));
                }
            }
        }
    }
}

// ------------------------------------------------------------------ launch
extern "C" void kernel_launch(void* const* d_in, const int* in_sizes, int n_in,
                              void* d_out, int out_size) {
    const float* x        = (const float*)d_in[0];
    const float* w_route  = (const float*)d_in[1];
    const float* b_route  = (const float*)d_in[2];
    const float* w_expert = (const float*)d_in[3];
    const float* bn_gamma = (const float*)d_in[4];
    const float* bn_beta  = (const float*)d_in[5];
    const float* bn_mean  = (const float*)d_in[6];
    const float* bn_var   = (const float*)d_in[7];
    float* out = (float*)d_out;

    cudaFuncSetAttribute(conv_mma_kernel,
                         cudaFuncAttributeMaxDynamicSharedMemorySize, SMEM_TOTAL);

    pool_kernel<<<NB*NC, 128>>>(x);
    route_kernel<<<1, 64>>>(w_route, b_route);
    fold_kernel<<<SEXP/256, 256>>>(w_expert);
    dim3 xg(NC/64, QP, NB);
    xpad_kernel<<<xg, 256>>>(x);
    dim3 grid(QTILES, NC/TILE_M, NB);
    conv_mma_kernel<<<grid, 256, SMEM_TOTAL>>>(bn_gamma, bn_beta, bn_mean, bn_var, out);
}